// round 9
// baseline (speedup 1.0000x reference)
#include <cuda_runtime.h>
#include <math.h>

// Problem constants
#define BATCH   256
#define SEQ     1024
#define INDIM   128
#define HID     512
#define CLS     128

// Kernel geometry
#define CLUSTER 8          // CTAs per cluster, each owns HS=64 hidden cols
#define BT      16         // batch rows per cluster
#define HS      64         // hidden slice per CTA
#define THREADS 256
#define HPAD    516        // h row stride in floats (2064B: 16B-aligned)
#define XPAD    132        // x row stride in floats (528B: 16B-aligned)

// Shared memory layout (in floats)
#define OFF_WHH 0
#define OFF_WXH (HID * HS)                       // 32768
#define OFF_H   (OFF_WXH + INDIM * HS)           // 40960
#define OFF_X   (OFF_H + BT * HPAD)              // 49216
#define SMEM_FLOATS (OFF_X + 2 * BT * XPAD)      // 53440
#define SMEM_BYTES  (SMEM_FLOATS * 4)            // 213760 B

// Ping-pong global exchange buffer for h (static device alloc: allowed)
__device__ float g_h[2][BATCH][HID];

// Split cluster barrier (release on arrive, acquire on wait — proven by
// R3/R5 bit-identity + R8 pass)
__device__ __forceinline__ void cluster_arrive_() {
    asm volatile("barrier.cluster.arrive.aligned;" ::: "memory");
}
__device__ __forceinline__ void cluster_wait_() {
    asm volatile("barrier.cluster.wait.aligned;" ::: "memory");
}

// ---------------------------------------------------------------------------
// XLA EmitFastTanh (f32, with_fma): exact reproduction (proven rel_err = 0.0)
// ---------------------------------------------------------------------------
__device__ __forceinline__ float xla_tanh(float x) {
    float xc = fminf(fmaxf(x, -7.99881172180175781f), 7.99881172180175781f);
    float x2 = __fmul_rn(xc, xc);
    float p = -2.76076847742355e-16f;
    p = __fmaf_rn(x2, p, 2.00018790482477e-13f);
    p = __fmaf_rn(x2, p, -8.60467152213735e-11f);
    p = __fmaf_rn(x2, p, 5.12229709037114e-08f);
    p = __fmaf_rn(x2, p, 1.48572235717979e-05f);
    p = __fmaf_rn(x2, p, 6.37261928875436e-04f);
    p = __fmaf_rn(x2, p, 4.89352455891786e-03f);
    p = __fmul_rn(xc, p);
    float q = 1.19825839466702e-06f;
    q = __fmaf_rn(x2, q, 1.18534705686654e-04f);
    q = __fmaf_rn(x2, q, 2.26843463243900e-03f);
    q = __fmaf_rn(x2, q, 4.89352518554385e-03f);
    float r = __fdiv_rn(p, q);
    return (fabsf(x) < 0.0004f) ? x : r;
}

// One k-quad of the 1x4 tile GEMM: h broadcast LDS.128 + 4x w LDS.128.
// Ascending-k FMA order per accumulator (bit-exact contract).
#define GEMM_QUAD(acc0, acc1, acc2, acc3, srcrow, W, kk)                       \
    {                                                                          \
        float4 hv = *(const float4*)((srcrow) + (kk));                         \
        float4 wA = *(const float4*)((W) + (kk) * HS);                         \
        float4 wB = *(const float4*)((W) + ((kk) + 1) * HS);                   \
        float4 wC = *(const float4*)((W) + ((kk) + 2) * HS);                   \
        float4 wD = *(const float4*)((W) + ((kk) + 3) * HS);                   \
        acc0 = __fmaf_rn(hv.x, wA.x, acc0); acc0 = __fmaf_rn(hv.y, wB.x, acc0);\
        acc0 = __fmaf_rn(hv.z, wC.x, acc0); acc0 = __fmaf_rn(hv.w, wD.x, acc0);\
        acc1 = __fmaf_rn(hv.x, wA.y, acc1); acc1 = __fmaf_rn(hv.y, wB.y, acc1);\
        acc1 = __fmaf_rn(hv.z, wC.y, acc1); acc1 = __fmaf_rn(hv.w, wD.y, acc1);\
        acc2 = __fmaf_rn(hv.x, wA.z, acc2); acc2 = __fmaf_rn(hv.y, wB.z, acc2);\
        acc2 = __fmaf_rn(hv.z, wC.z, acc2); acc2 = __fmaf_rn(hv.w, wD.z, acc2);\
        acc3 = __fmaf_rn(hv.x, wA.w, acc3); acc3 = __fmaf_rn(hv.y, wB.w, acc3);\
        acc3 = __fmaf_rn(hv.z, wC.w, acc3); acc3 = __fmaf_rn(hv.w, wD.w, acc3);\
    }

extern "C" __global__ void __cluster_dims__(CLUSTER, 1, 1) __launch_bounds__(THREADS, 1)
rnn_cluster_kernel(const float* __restrict__ x,
                   const float* __restrict__ Whh,
                   const float* __restrict__ Wxh,
                   const float* __restrict__ Why,
                   const float* __restrict__ bh,
                   const float* __restrict__ by,
                   float* __restrict__ out)
{
    extern __shared__ float sm[];
    float* whh = sm + OFF_WHH;   // [HID][HS]
    float* wxh = sm + OFF_WXH;   // [INDIM][HS]
    float* hsm = sm + OFF_H;     // [BT][HPAD]
    float* xsm = sm + OFF_X;     // [2][BT][XPAD]

    const int tid   = threadIdx.x;
    const int rank  = blockIdx.x % CLUSTER;
    const int cid   = blockIdx.x / CLUSTER;
    const int bbase = cid * BT;

    // ---- Prologue: weight slices into smem ----
    for (int i4 = tid; i4 < HID * (HS / 4); i4 += THREADS) {
        int k = i4 >> 4, j4 = i4 & 15;
        float4 v = __ldg((const float4*)(Whh + (size_t)k * HID + rank * HS) + j4);
        *((float4*)(whh + k * HS) + j4) = v;
    }
    for (int i4 = tid; i4 < INDIM * (HS / 4); i4 += THREADS) {
        int k = i4 >> 4, j4 = i4 & 15;
        float4 v = __ldg((const float4*)(Wxh + (size_t)k * HID + rank * HS) + j4);
        *((float4*)(wxh + k * HS) + j4) = v;
    }
    // h0 = 0
    for (int i = tid; i < BT * HPAD; i += THREADS) hsm[i] = 0.0f;

    // ---- Thread maps ----
    // Compute/publish/reload all share: row = tid>>4 (0..15), lane16 = tid&15
    const int row    = tid >> 4;
    const int lane16 = tid & 15;
    const int col0   = lane16 * 4;            // 4 hidden cols per thread
    const int gcol   = rank * HS + col0;
    const float* pwhh = whh + col0;
    const float* pwxh = wxh + col0;
    const float* hrow = hsm + row * HPAD;

    // Stage x(t=0) into buffer 0
    {
        const float* xb = x + (size_t)(bbase + row) * (SEQ * INDIM);
        float* xd = xsm + 0 * BT * XPAD + row * XPAD;
        ((float4*)xd)[lane16]      = __ldg((const float4*)xb + lane16);
        ((float4*)xd)[lane16 + 16] = __ldg((const float4*)xb + lane16 + 16);
    }
    __syncthreads();

    // ---- c(0): x(0) @ W_xh, ascending-k chain over 128 ----
    float c0 = 0.0f, c1 = 0.0f, c2 = 0.0f, c3 = 0.0f;
    {
        const float* xr = xsm + 0 * BT * XPAD + row * XPAD;
        #pragma unroll 4
        for (int k = 0; k < INDIM; k += 4)
            GEMM_QUAD(c0, c1, c2, c3, xr, pwxh, k)
    }

    // ---- Recurrent scan ----
    for (int t = 0; t < SEQ; ++t) {
        const int xb_nxt = (t + 1) & 1;
        const bool pf = (t + 1 < SEQ);

        // Prefetch x(t+1) into registers
        float4 xp0, xp1;
        if (pf) {
            const float* xb = x + ((size_t)(bbase + row) * SEQ + (t + 1)) * INDIM;
            xp0 = __ldg((const float4*)xb + lane16);
            xp1 = __ldg((const float4*)xb + lane16 + 16);
        }

        // --- a = h(t) @ W_hh: ascending-k chain over 512 (k-quad blocks) ---
        float a0 = 0.0f, a1 = 0.0f, a2 = 0.0f, a3 = 0.0f;
        #pragma unroll 4
        for (int k = 0; k < HID; k += 4)
            GEMM_QUAD(a0, a1, a2, a3, hrow, pwhh, k)

        // pre = c + a (single fadd join), exact XLA tanh, publish 1x STG.128
        float4 v;
        v.x = xla_tanh(__fadd_rn(c0, a0));
        v.y = xla_tanh(__fadd_rn(c1, a1));
        v.z = xla_tanh(__fadd_rn(c2, a2));
        v.w = xla_tanh(__fadd_rn(c3, a3));

        const int buf = t & 1;
        *(float4*)&g_h[buf][bbase + row][gcol] = v;

        // Release our h stores; stage x(t+1) while peers arrive
        cluster_arrive_();
        if (pf) {
            float* xd = xsm + xb_nxt * BT * XPAD + row * XPAD;
            ((float4*)xd)[lane16]      = xp0;
            ((float4*)xd)[lane16 + 16] = xp1;
        }
        __syncthreads();   // xsm[nxt] visible for c-loop

        // c-half1 (k 0..63): hides cluster straggle before wait
        c0 = 0.0f; c1 = 0.0f; c2 = 0.0f; c3 = 0.0f;
        const float* xr = xsm + xb_nxt * BT * XPAD + row * XPAD;
        if (pf) {
            #pragma unroll 4
            for (int k = 0; k < INDIM / 2; k += 4)
                GEMM_QUAD(c0, c1, c2, c3, xr, pwxh, k)
        }

        // Acquire peers' h stores
        cluster_wait_();

        // Issue all 8 reload LDGs (L2-only), then hide their latency under
        // c-half2 before the dependent STS.
        float4 g0, g1, g2, g3, g4, g5, g6, g7;
        {
            const float4* gsrc = (const float4*)&g_h[buf][bbase + row][0];
            g0 = __ldcg(gsrc + (lane16 +   0));
            g1 = __ldcg(gsrc + (lane16 +  16));
            g2 = __ldcg(gsrc + (lane16 +  32));
            g3 = __ldcg(gsrc + (lane16 +  48));
            g4 = __ldcg(gsrc + (lane16 +  64));
            g5 = __ldcg(gsrc + (lane16 +  80));
            g6 = __ldcg(gsrc + (lane16 +  96));
            g7 = __ldcg(gsrc + (lane16 + 112));
        }

        // c-half2 (k 64..127): overlaps the LDG round-trip
        if (pf) {
            #pragma unroll 4
            for (int k = INDIM / 2; k < INDIM; k += 4)
                GEMM_QUAD(c0, c1, c2, c3, xr, pwxh, k)
        }

        // Commit h(t+1) into smem
        {
            float* hdst = hsm + row * HPAD;
            ((float4*)hdst)[lane16 +   0] = g0;
            ((float4*)hdst)[lane16 +  16] = g1;
            ((float4*)hdst)[lane16 +  32] = g2;
            ((float4*)hdst)[lane16 +  48] = g3;
            ((float4*)hdst)[lane16 +  64] = g4;
            ((float4*)hdst)[lane16 +  80] = g5;
            ((float4*)hdst)[lane16 +  96] = g6;
            ((float4*)hdst)[lane16 + 112] = g7;
        }
        __syncthreads();
    }

    // ---- Epilogue: out = h_final @ Why + by (ascending-k per output) ----
    {
        const int gc = rank * 16 + lane16;
        float acc = 0.0f;
        const float* hr = hsm + row * HPAD;
        #pragma unroll 8
        for (int k = 0; k < HID; ++k)
            acc = __fmaf_rn(hr[k], __ldg(Why + (size_t)k * CLS + gc), acc);
        out[(bbase + row) * CLS + gc] = __fadd_rn(acc, by[gc]);
    }
}

extern "C" void kernel_launch(void* const* d_in, const int* in_sizes, int n_in,
                              void* d_out, int out_size)
{
    const float* x   = (const float*)d_in[0];  // [256,1024,128]
    const float* Whh = (const float*)d_in[1];  // [512,512]
    const float* Wxh = (const float*)d_in[2];  // [128,512]
    const float* Why = (const float*)d_in[3];  // [512,128]
    const float* bh  = (const float*)d_in[4];  // [512]
    const float* by  = (const float*)d_in[5];  // [128]
    float* out = (float*)d_out;                // [256,128]

    cudaFuncSetAttribute(rnn_cluster_kernel,
                         cudaFuncAttributeMaxDynamicSharedMemorySize, SMEM_BYTES);

    dim3 grid((BATCH / BT) * CLUSTER);  // 128 CTAs = 16 clusters of 8
    dim3 block(THREADS);
    rnn_cluster_kernel<<<grid, block, SMEM_BYTES>>>(x, Whh, Wxh, Why, bh, by, out);
}